// round 13
// baseline (speedup 1.0000x reference)
#include <cuda_runtime.h>
#include <math.h>

#define NTHR  256
#define MELB  250                       // mel: 250 blocks * 8 warps * 128 quads = 256000
#define DCBLK 240                       // dc: 240 blocks * 256 thr = 61440 = 2 thr/row
#define NBLK  (MELB + DCBLK + 2)        // 492 total; last 2 = stop blocks

// problem shape (fixed by setup_inputs)
#define Bc    16
#define Tc    800
#define NMELc 80
#define Nc    3
#define Hc    4
#define Sc    160
#define Kc    5                         // Tc / Sc
#define NM4   20                        // NMELc / 4

__device__ double g_mel, g_dc, g_stop;
__device__ int g_mask_cnt;
__device__ unsigned long long g_len_sum;
__device__ unsigned int g_done;

__global__ __launch_bounds__(NTHR)
void loss_kernel(const int* __restrict__ lengths,
                 const int* __restrict__ mask,          // JAX bool -> int32
                 const float* __restrict__ stop_pred,
                 const float4* __restrict__ mels_pred,
                 const float4* __restrict__ mels_target,
                 const float* __restrict__ align,
                 float* __restrict__ out)
{
    const int tid  = threadIdx.x;
    const int bid  = blockIdx.x;
    const int lane = tid & 31;
    const int warp = tid >> 5;

    if (bid < MELB) {
        // ---- mel L1: each warp covers 128 consecutive quads;
        //      4 lane-interleaved float4-pairs, loads front-batched ----
        const int gw = bid * (NTHR / 32) + warp;
        const int q0 = gw * 128 + lane;
        float4 p[4], g[4];
        float  m[4];
        #pragma unroll
        for (int j = 0; j < 4; j++) {
            const int q = q0 + j * 32;
            p[j] = __ldg(&mels_pred[q]);
            g[j] = __ldg(&mels_target[q]);
            m[j] = __ldg(&mask[(unsigned)q / NM4]) ? 1.0f : 0.0f;
        }
        float acc = 0.0f;
        #pragma unroll
        for (int j = 0; j < 4; j++) {
            acc += fabsf(fmaf(p[j].x, m[j], -g[j].x)) + fabsf(fmaf(p[j].y, m[j], -g[j].y))
                 + fabsf(fmaf(p[j].z, m[j], -g[j].z)) + fabsf(fmaf(p[j].w, m[j], -g[j].w));
        }
        #pragma unroll
        for (int o = 16; o; o >>= 1) acc += __shfl_xor_sync(0xffffffffu, acc, o);
        __shared__ float s_m[NTHR / 32];
        if (lane == 0) s_m[warp] = acc;
        __syncthreads();
        if (tid == 0) {
            float tm = 0.0f;
            #pragma unroll
            for (int i = 0; i < NTHR / 32; i++) tm += s_m[i];
            atomicAdd(&g_mel, (double)tm);
        }
    } else if (bid < MELB + DCBLK) {
        // ---- dc band sum: TWO threads per (n,bh,s) row, 3 quads each.
        // band[s,t] nonzero iff k*t-50 <= s < k*t+50 -> contiguous t-window
        // of width <= 20 floats -> at most 6 float4 quads per row. ----
        const int gt   = (bid - MELB) * NTHR + tid;
        const int r    = gt >> 1;
        const int half = gt & 1;
        const int s     = r % Sc;
        const int plane = r / Sc;
        const int b     = (plane % (Bc * Hc)) % Bc;    // reshape (n,H,B): b = bh % B
        float acc = 0.0f;
        if (Tc >= __ldg(&lengths[b])) {                 // bmask
            const int t_lo = (s >= 50) ? ((s - 50) / Kc + 1) : 0;   // s < k*t+50
            int t_hi = (s + 50) / Kc + 1;                            // k*t-50 <= s
            if (t_hi > Tc) t_hi = Tc;
            const int q_lo = t_lo >> 2;
            const int q_hi = (t_hi + 3) >> 2;
            const float4* row = (const float4*)(align + (size_t)r * Tc);
            const int j0 = half * 3;
            float4 v[3];
            #pragma unroll
            for (int j = 0; j < 3; j++) {
                const int qq = q_lo + j0 + j;
                v[j] = (qq < q_hi) ? __ldg(&row[qq]) : make_float4(0.f,0.f,0.f,0.f);
            }
            #pragma unroll
            for (int j = 0; j < 3; j++) {
                const int t0 = (q_lo + j0 + j) << 2;
                acc += ((t0     >= t_lo && t0     < t_hi) ? v[j].x : 0.0f)
                     + ((t0 + 1 >= t_lo && t0 + 1 < t_hi) ? v[j].y : 0.0f)
                     + ((t0 + 2 >= t_lo && t0 + 2 < t_hi) ? v[j].z : 0.0f)
                     + ((t0 + 3 >= t_lo && t0 + 3 < t_hi) ? v[j].w : 0.0f);
            }
        }
        #pragma unroll
        for (int o = 16; o; o >>= 1) acc += __shfl_xor_sync(0xffffffffu, acc, o);
        __shared__ float s_d[NTHR / 32];
        if (lane == 0) s_d[warp] = acc;
        __syncthreads();
        if (tid == 0) {
            float td = 0.0f;
            #pragma unroll
            for (int i = 0; i < NTHR / 32; i++) td += s_d[i];
            atomicAdd(&g_dc, (double)td);
        }
    } else {
        // ---- stop BCE: one warp per batch row (last 2 blocks) ----
        const int b = (bid - MELB - DCBLK) * (NTHR / 32) + warp;   // 0..15
        if (b < Bc) {
            int cnt = 0, maxi = -1;
            const int* mrow = mask + b * Tc;
            #pragma unroll 5
            for (int t = lane; t < Tc; t += 32)
                if (mrow[t]) { cnt++; maxi = t; }       // t increasing: lane-max = last true
            #pragma unroll
            for (int o = 16; o; o >>= 1) {
                cnt += __shfl_xor_sync(0xffffffffu, cnt, o);
                int m2 = __shfl_xor_sync(0xffffffffu, maxi, o);
                maxi = max(maxi, m2);
            }
            if (lane == 0) {
                atomicAdd(&g_mask_cnt, cnt);
                const int idx = (maxi < 0) ? 0 : maxi;
                float lg = logf(stop_pred[b * Tc + idx]);
                if (lg < -100.0f) lg = -100.0f;
                atomicAdd(&g_stop, (double)(-5.0f * lg));   // STOP_WEIGHT = 5
            }
        }
        if (bid == MELB + DCBLK && tid == 0) {
            unsigned long long ls = 0;
            #pragma unroll
            for (int b2 = 0; b2 < Bc; b2++) ls += (unsigned long long)__ldg(&lengths[b2]);
            atomicAdd(&g_len_sum, ls);
        }
    }

    // ---- last-done block finalizes ----
    __threadfence();
    __shared__ unsigned int s_last;
    if (tid == 0) {
        unsigned int prev = atomicAdd(&g_done, 1u);
        s_last = (prev == NBLK - 1) ? 1u : 0u;
    }
    __syncthreads();
    if (s_last && tid == 0) {
        double mel = atomicAdd(&g_mel, 0.0);
        double dc  = atomicAdd(&g_dc, 0.0);
        double st  = atomicAdd(&g_stop, 0.0);
        int    mc  = atomicAdd(&g_mask_cnt, 0);
        unsigned long long ls = atomicAdd(&g_len_sum, 0ull);

        double mel_loss  = mel / ((double)Bc * (double)Tc * (double)NMELc);
        double stop_loss = st / (double)mc;
        double dcv = dc / ((double)Hc * (double)ls * (double)Nc);
        out[0] = (float)(mel_loss + stop_loss - 1e-4 * dcv);  // DC_STRENGTH = 1e-4

        g_mel = 0.0; g_dc = 0.0; g_stop = 0.0;
        g_mask_cnt = 0; g_len_sum = 0ull; g_done = 0u;
        __threadfence();
    }
}

extern "C" void kernel_launch(void* const* d_in, const int* in_sizes, int n_in,
                              void* d_out, int out_size)
{
    const int*    lengths     = (const int*)d_in[0];
    const int*    mask        = (const int*)d_in[1];     // bool -> int32
    const float*  stop_pred   = (const float*)d_in[2];
    const float4* mels_pred   = (const float4*)d_in[3];
    const float4* mels_target = (const float4*)d_in[4];
    const float*  align       = (const float*)d_in[5];

    loss_kernel<<<NBLK, NTHR>>>(lengths, mask, stop_pred, mels_pred, mels_target,
                                align, (float*)d_out);
}

// round 14
// speedup vs baseline: 1.0435x; 1.0435x over previous
#include <cuda_runtime.h>
#include <math.h>
#include <stdint.h>

#define NTHR  256
#define MELB  250                       // mel: 250 blocks * 1024 quads = 256000 quads
#define DCBLK 240                       // dc: 240 blocks * 256 thr = 61440 = 2 thr/row
#define NBLK  (MELB + DCBLK + 2)        // 492 total; last 2 = stop blocks

// problem shape (fixed by setup_inputs)
#define Bc    16
#define Tc    800
#define NMELc 80
#define Nc    3
#define Hc    4
#define Sc    160
#define Kc    5                         // Tc / Sc
#define NM4   20                        // NMELc / 4
#define MQ    1024                      // quads per mel block
#define MBYTES (MQ * 16)                // 16384 bytes per array per block

__device__ double g_mel, g_dc, g_stop;
__device__ int g_mask_cnt;
__device__ unsigned long long g_len_sum;
__device__ unsigned int g_done;

__device__ __forceinline__ uint32_t smem_u32(const void* p) {
    return (uint32_t)__cvta_generic_to_shared(p);
}

__global__ __launch_bounds__(NTHR)
void loss_kernel(const int* __restrict__ lengths,
                 const int* __restrict__ mask,          // JAX bool -> int32
                 const float* __restrict__ stop_pred,
                 const float* __restrict__ mels_pred,
                 const float* __restrict__ mels_target,
                 const float* __restrict__ align,
                 float* __restrict__ out)
{
    const int tid  = threadIdx.x;
    const int bid  = blockIdx.x;
    const int lane = tid & 31;
    const int warp = tid >> 5;

    __shared__ alignas(16) float4 s_pred[MQ];
    __shared__ alignas(16) float4 s_tgt[MQ];
    __shared__ float s_maskv[56];
    __shared__ alignas(8) unsigned long long s_mbar;
    __shared__ float s_red[NTHR / 32];

    if (bid < MELB) {
        // ---- mel L1 via cp.async.bulk: 2 x 16KB engine copies per block ----
        const int Q0     = bid * MQ;
        const int base_m = Q0 / NM4;
        const uint32_t mb = smem_u32(&s_mbar);

        if (tid == 0)
            asm volatile("mbarrier.init.shared.b64 [%0], 1;" :: "r"(mb) : "memory");
        if (tid < 53) {                       // stage mask values for this block
            int mi = base_m + tid;
            if (mi > Bc * Tc - 1) mi = Bc * Tc - 1;
            s_maskv[tid] = __ldg(&mask[mi]) ? 1.0f : 0.0f;
        }
        __syncthreads();                      // mbar init + mask visible

        if (tid == 0) {
            asm volatile("mbarrier.arrive.expect_tx.shared.b64 _, [%0], %1;"
                         :: "r"(mb), "r"(2 * MBYTES) : "memory");
            asm volatile("cp.async.bulk.shared::cta.global.mbarrier::complete_tx::bytes"
                         " [%0], [%1], %2, [%3];"
                         :: "r"(smem_u32(s_pred)),
                            "l"(mels_pred + (size_t)Q0 * 4), "r"(MBYTES), "r"(mb)
                         : "memory");
            asm volatile("cp.async.bulk.shared::cta.global.mbarrier::complete_tx::bytes"
                         " [%0], [%1], %2, [%3];"
                         :: "r"(smem_u32(s_tgt)),
                            "l"(mels_target + (size_t)Q0 * 4), "r"(MBYTES), "r"(mb)
                         : "memory");
        }
        // all threads wait for the copies (acquire orders smem reads)
        asm volatile(
            "{\n\t.reg .pred P;\n"
            "W%=:\n\t"
            "mbarrier.try_wait.parity.acquire.cta.shared::cta.b64 P, [%0], 0, 0x989680;\n\t"
            "@P bra D%=;\n\t"
            "bra W%=;\n"
            "D%=:\n\t}"
            :: "r"(mb) : "memory");

        float acc = 0.0f;
        #pragma unroll
        for (int j = 0; j < 4; j++) {
            const int ql = tid + j * NTHR;               // conflict-free LDS.128
            float4 p = s_pred[ql];
            float4 g = s_tgt[ql];
            float  m = s_maskv[(unsigned)(Q0 + ql) / NM4 - base_m];
            acc += fabsf(fmaf(p.x, m, -g.x)) + fabsf(fmaf(p.y, m, -g.y))
                 + fabsf(fmaf(p.z, m, -g.z)) + fabsf(fmaf(p.w, m, -g.w));
        }
        #pragma unroll
        for (int o = 16; o; o >>= 1) acc += __shfl_xor_sync(0xffffffffu, acc, o);
        if (lane == 0) s_red[warp] = acc;
        __syncthreads();
        if (tid == 0) {
            float tm = 0.0f;
            #pragma unroll
            for (int i = 0; i < NTHR / 32; i++) tm += s_red[i];
            atomicAdd(&g_mel, (double)tm);
        }
    } else if (bid < MELB + DCBLK) {
        // ---- dc band sum: TWO threads per (n,bh,s) row, 3 quads each.
        // band[s,t] nonzero iff k*t-50 <= s < k*t+50 -> contiguous t-window
        // of width <= 20 floats -> at most 6 float4 quads per row. ----
        const int gt   = (bid - MELB) * NTHR + tid;
        const int r    = gt >> 1;
        const int half = gt & 1;
        const int s     = r % Sc;
        const int plane = r / Sc;
        const int b     = (plane % (Bc * Hc)) % Bc;    // reshape (n,H,B): b = bh % B
        float acc = 0.0f;
        if (Tc >= __ldg(&lengths[b])) {                 // bmask
            const int t_lo = (s >= 50) ? ((s - 50) / Kc + 1) : 0;   // s < k*t+50
            int t_hi = (s + 50) / Kc + 1;                            // k*t-50 <= s
            if (t_hi > Tc) t_hi = Tc;
            const int q_lo = t_lo >> 2;
            const int q_hi = (t_hi + 3) >> 2;
            const float4* row = (const float4*)(align + (size_t)r * Tc);
            const int j0 = half * 3;
            float4 v[3];
            #pragma unroll
            for (int j = 0; j < 3; j++) {
                const int qq = q_lo + j0 + j;
                v[j] = (qq < q_hi) ? __ldg(&row[qq]) : make_float4(0.f,0.f,0.f,0.f);
            }
            #pragma unroll
            for (int j = 0; j < 3; j++) {
                const int t0 = (q_lo + j0 + j) << 2;
                acc += ((t0     >= t_lo && t0     < t_hi) ? v[j].x : 0.0f)
                     + ((t0 + 1 >= t_lo && t0 + 1 < t_hi) ? v[j].y : 0.0f)
                     + ((t0 + 2 >= t_lo && t0 + 2 < t_hi) ? v[j].z : 0.0f)
                     + ((t0 + 3 >= t_lo && t0 + 3 < t_hi) ? v[j].w : 0.0f);
            }
        }
        #pragma unroll
        for (int o = 16; o; o >>= 1) acc += __shfl_xor_sync(0xffffffffu, acc, o);
        if (lane == 0) s_red[warp] = acc;
        __syncthreads();
        if (tid == 0) {
            float td = 0.0f;
            #pragma unroll
            for (int i = 0; i < NTHR / 32; i++) td += s_red[i];
            atomicAdd(&g_dc, (double)td);
        }
    } else {
        // ---- stop BCE: one warp per batch row (last 2 blocks) ----
        const int b = (bid - MELB - DCBLK) * (NTHR / 32) + warp;   // 0..15
        if (b < Bc) {
            int cnt = 0, maxi = -1;
            const int* mrow = mask + b * Tc;
            #pragma unroll 5
            for (int t = lane; t < Tc; t += 32)
                if (mrow[t]) { cnt++; maxi = t; }       // t increasing: lane-max = last true
            #pragma unroll
            for (int o = 16; o; o >>= 1) {
                cnt += __shfl_xor_sync(0xffffffffu, cnt, o);
                int m2 = __shfl_xor_sync(0xffffffffu, maxi, o);
                maxi = max(maxi, m2);
            }
            if (lane == 0) {
                atomicAdd(&g_mask_cnt, cnt);
                const int idx = (maxi < 0) ? 0 : maxi;
                float lg = logf(stop_pred[b * Tc + idx]);
                if (lg < -100.0f) lg = -100.0f;
                atomicAdd(&g_stop, (double)(-5.0f * lg));   // STOP_WEIGHT = 5
            }
        }
        if (bid == MELB + DCBLK && tid == 0) {
            unsigned long long ls = 0;
            #pragma unroll
            for (int b2 = 0; b2 < Bc; b2++) ls += (unsigned long long)__ldg(&lengths[b2]);
            atomicAdd(&g_len_sum, ls);
        }
    }

    // ---- last-done block finalizes ----
    __threadfence();
    __shared__ unsigned int s_last;
    if (tid == 0) {
        unsigned int prev = atomicAdd(&g_done, 1u);
        s_last = (prev == NBLK - 1) ? 1u : 0u;
    }
    __syncthreads();
    if (s_last && tid == 0) {
        double mel = atomicAdd(&g_mel, 0.0);
        double dc  = atomicAdd(&g_dc, 0.0);
        double st  = atomicAdd(&g_stop, 0.0);
        int    mc  = atomicAdd(&g_mask_cnt, 0);
        unsigned long long ls = atomicAdd(&g_len_sum, 0ull);

        double mel_loss  = mel / ((double)Bc * (double)Tc * (double)NMELc);
        double stop_loss = st / (double)mc;
        double dcv = dc / ((double)Hc * (double)ls * (double)Nc);
        out[0] = (float)(mel_loss + stop_loss - 1e-4 * dcv);  // DC_STRENGTH = 1e-4

        g_mel = 0.0; g_dc = 0.0; g_stop = 0.0;
        g_mask_cnt = 0; g_len_sum = 0ull; g_done = 0u;
        __threadfence();
    }
}

extern "C" void kernel_launch(void* const* d_in, const int* in_sizes, int n_in,
                              void* d_out, int out_size)
{
    const int*   lengths     = (const int*)d_in[0];
    const int*   mask        = (const int*)d_in[1];     // bool -> int32
    const float* stop_pred   = (const float*)d_in[2];
    const float* mels_pred   = (const float*)d_in[3];
    const float* mels_target = (const float*)d_in[4];
    const float* align       = (const float*)d_in[5];

    loss_kernel<<<NBLK, NTHR>>>(lengths, mask, stop_pred, mels_pred, mels_target,
                                align, (float*)d_out);
}